// round 6
// baseline (speedup 1.0000x reference)
#include <cuda_runtime.h>
#include <math.h>

#define SEQT 512
#define NB   256
#define OBS  128
#define LAT  64
#define HID  256
#define MB   (SEQT*NB)

// ------------------------- device scratch ----------------------------------
__device__ float g_h1   [(size_t)MB*HID];
__device__ float g_phix [(size_t)MB*HID];
__device__ float g_encx [(size_t)MB*HID];           // includes enc_b1
__device__ float g_gxx  [(size_t)MB*3*HID];         // includes gru_bih
__device__ float g_h    [2][NB*HID];
__device__ float g_Ep   [4][NB*HID];
__device__ float g_Ap   [4][NB*HID];
__device__ float g_GHp  [4][NB*3*HID];
__device__ float g_D1hp [2][4][NB*HID];
__device__ float g_postp[4][NB*2*LAT];
__device__ float g_priorp[4][NB*2*LAT];
__device__ float g_phiz [NB*HID];
__device__ float g_gxzp [4][NB*3*HID];
__device__ float g_Dp   [4][NB*HID];
__device__ float g_recp [4][NB*OBS];

__device__ unsigned          g_bar_cnt;
__device__ volatile unsigned g_bar_gen;

#define PSTR_H   ((size_t)NB*HID)
#define PSTR_L   ((size_t)NB*2*LAT)

// ------------------------- grid barrier ------------------------------------
__device__ __forceinline__ void grid_sync()
{
    __syncthreads();
    if (threadIdx.x == 0) {
        __threadfence();
        unsigned my = g_bar_gen;
        if (atomicAdd(&g_bar_cnt, 1u) == gridDim.x - 1u) {
            g_bar_cnt = 0u;
            __threadfence();
            g_bar_gen = my + 1u;
        } else {
            while (g_bar_gen == my) { __nanosleep(20); }
        }
        __threadfence();
    }
    __syncthreads();
}

// ------------------------- 128x64 GEMM tile (xNK chunks of 64) --------------
// C[row0..+128, col0..+64] = epi( Aop[rows, kA0..+64*nk] @ W[col0..+64, kW0..+64*nk]^T )
// aSel 0: plain A.   aSel 1: relu( sum4(A partials) [+sum4(B2)] [+add] [+abias] )
// aSel 2: z-gen: pm/pl = sum4(postp)+abias halves; z = pm + eps*exp(0.5*pl)
__device__ __noinline__ void tile128(
    int aSel,
    const float* __restrict__ A, size_t lda, int kA0,
    const float* __restrict__ B2, size_t pstr,
    const float* __restrict__ add, const float* __restrict__ abias,
    const float* __restrict__ epsT,
    const float* __restrict__ W, int ldw, int kW0,
    int nk, int row0, int col0,
    float* __restrict__ C, size_t ldc,
    const float* __restrict__ cbias, int crelu)
{
    __shared__ float sA[64*128];   // [k][row]
    __shared__ float sW[64*64];    // [k][col]
    const int tid = threadIdx.x;
    const int rA = tid & 127, qA = tid >> 7;   // A loader: row, k-phase (0..1)
    const int rW = tid & 63,  qW = tid >> 6;   // W loader: col, k-phase (0..3)
    const int r0 = (tid >> 4) << 3;            // compute: 8 rows
    const int c0 = (tid & 15) << 2;            // compute: 4 cols

    float acc[32];
#pragma unroll
    for (int i = 0; i < 32; i++) acc[i] = 0.f;

    for (int kc = 0; kc < nk; kc++) {
        const int kA = kA0 + kc * 64, kW = kW0 + kc * 64;
        // ---- load A (8 float4/thread), transpose into k-major ----
#pragma unroll
        for (int j = 0; j < 8; j++) {
            int k = (qA + j * 2) * 4;
            float4 v;
            if (aSel == 0) {
                v = *(const float4*)(A + (size_t)(row0 + rA) * lda + kA + k);
            } else if (aSel == 1) {
                const float* p = A + (size_t)(row0 + rA) * lda + kA + k;
                float4 s0 = *(const float4*)(p);
                float4 s1 = *(const float4*)(p + pstr);
                float4 s2 = *(const float4*)(p + 2 * pstr);
                float4 s3 = *(const float4*)(p + 3 * pstr);
                v.x = s0.x+s1.x+s2.x+s3.x; v.y = s0.y+s1.y+s2.y+s3.y;
                v.z = s0.z+s1.z+s2.z+s3.z; v.w = s0.w+s1.w+s2.w+s3.w;
                if (B2) {
                    const float* p2 = B2 + (size_t)(row0 + rA) * lda + kA + k;
                    float4 t0 = *(const float4*)(p2);
                    float4 t1 = *(const float4*)(p2 + pstr);
                    float4 t2 = *(const float4*)(p2 + 2 * pstr);
                    float4 t3 = *(const float4*)(p2 + 3 * pstr);
                    v.x += t0.x+t1.x+t2.x+t3.x; v.y += t0.y+t1.y+t2.y+t3.y;
                    v.z += t0.z+t1.z+t2.z+t3.z; v.w += t0.w+t1.w+t2.w+t3.w;
                }
                if (add) {
                    float4 a4 = *(const float4*)(add + (size_t)(row0 + rA) * lda + kA + k);
                    v.x += a4.x; v.y += a4.y; v.z += a4.z; v.w += a4.w;
                }
                if (abias) {
                    float4 b4 = *(const float4*)(abias + kA + k);
                    v.x += b4.x; v.y += b4.y; v.z += b4.z; v.w += b4.w;
                }
                v.x = fmaxf(v.x, 0.f); v.y = fmaxf(v.y, 0.f);
                v.z = fmaxf(v.z, 0.f); v.w = fmaxf(v.w, 0.f);
            } else {
                int rg = row0 + rA;
                const float* pm0 = A + (size_t)rg * 128 + k;
                const float* pl0 = A + (size_t)rg * 128 + 64 + k;
                float4 m0 = *(const float4*)(pm0);
                float4 m1 = *(const float4*)(pm0 + pstr);
                float4 m2 = *(const float4*)(pm0 + 2 * pstr);
                float4 m3 = *(const float4*)(pm0 + 3 * pstr);
                float4 l0 = *(const float4*)(pl0);
                float4 l1 = *(const float4*)(pl0 + pstr);
                float4 l2 = *(const float4*)(pl0 + 2 * pstr);
                float4 l3 = *(const float4*)(pl0 + 3 * pstr);
                float4 bm = *(const float4*)(abias + k);
                float4 bl = *(const float4*)(abias + 64 + k);
                float4 ev = *(const float4*)(epsT + (size_t)rg * 64 + k);
                float pmx = m0.x+m1.x+m2.x+m3.x+bm.x, plx = l0.x+l1.x+l2.x+l3.x+bl.x;
                float pmy = m0.y+m1.y+m2.y+m3.y+bm.y, ply = l0.y+l1.y+l2.y+l3.y+bl.y;
                float pmz = m0.z+m1.z+m2.z+m3.z+bm.z, plz = l0.z+l1.z+l2.z+l3.z+bl.z;
                float pmw = m0.w+m1.w+m2.w+m3.w+bm.w, plw = l0.w+l1.w+l2.w+l3.w+bl.w;
                v.x = pmx + ev.x * expf(0.5f * plx);
                v.y = pmy + ev.y * expf(0.5f * ply);
                v.z = pmz + ev.z * expf(0.5f * plz);
                v.w = pmw + ev.w * expf(0.5f * plw);
            }
            sA[(k + 0) * 128 + rA] = v.x;
            sA[(k + 1) * 128 + rA] = v.y;
            sA[(k + 2) * 128 + rA] = v.z;
            sA[(k + 3) * 128 + rA] = v.w;
        }
        // ---- load W (4 float4/thread) ----
#pragma unroll
        for (int j = 0; j < 4; j++) {
            int k = (qW + j * 4) * 4;
            float4 wv = *(const float4*)(W + (size_t)(col0 + rW) * ldw + kW + k);
            sW[(k + 0) * 64 + rW] = wv.x;
            sW[(k + 1) * 64 + rW] = wv.y;
            sW[(k + 2) * 64 + rW] = wv.z;
            sW[(k + 3) * 64 + rW] = wv.w;
        }
        __syncthreads();
#pragma unroll 4
        for (int kk = 0; kk < 64; kk++) {
            float4 a0 = *(const float4*)(sA + kk * 128 + r0);
            float4 a1 = *(const float4*)(sA + kk * 128 + r0 + 4);
            float4 w  = *(const float4*)(sW + kk * 64 + c0);
            acc[0]  += a0.x*w.x; acc[1]  += a0.x*w.y; acc[2]  += a0.x*w.z; acc[3]  += a0.x*w.w;
            acc[4]  += a0.y*w.x; acc[5]  += a0.y*w.y; acc[6]  += a0.y*w.z; acc[7]  += a0.y*w.w;
            acc[8]  += a0.z*w.x; acc[9]  += a0.z*w.y; acc[10] += a0.z*w.z; acc[11] += a0.z*w.w;
            acc[12] += a0.w*w.x; acc[13] += a0.w*w.y; acc[14] += a0.w*w.z; acc[15] += a0.w*w.w;
            acc[16] += a1.x*w.x; acc[17] += a1.x*w.y; acc[18] += a1.x*w.z; acc[19] += a1.x*w.w;
            acc[20] += a1.y*w.x; acc[21] += a1.y*w.y; acc[22] += a1.y*w.z; acc[23] += a1.y*w.w;
            acc[24] += a1.z*w.x; acc[25] += a1.z*w.y; acc[26] += a1.z*w.z; acc[27] += a1.z*w.w;
            acc[28] += a1.w*w.x; acc[29] += a1.w*w.y; acc[30] += a1.w*w.z; acc[31] += a1.w*w.w;
        }
        __syncthreads();
    }

    float4 cb = make_float4(0.f, 0.f, 0.f, 0.f);
    if (cbias) cb = *(const float4*)(cbias + col0 + c0);
#pragma unroll
    for (int i = 0; i < 8; i++) {
        size_t row = (size_t)(row0 + r0 + i);
        float4 v;
        v.x = acc[i*4+0] + cb.x; v.y = acc[i*4+1] + cb.y;
        v.z = acc[i*4+2] + cb.z; v.w = acc[i*4+3] + cb.w;
        if (crelu) {
            v.x = fmaxf(v.x, 0.f); v.y = fmaxf(v.y, 0.f);
            v.z = fmaxf(v.z, 0.f); v.w = fmaxf(v.w, 0.f);
        }
        *(float4*)(C + row * ldc + col0 + c0) = v;
    }
}

// ------------------------- reduce helpers -----------------------------------
__device__ __forceinline__ void red_latent(int unit, const float (*P)[NB*2*LAT],
                                           const float* __restrict__ bias,
                                           float* __restrict__ om, float* __restrict__ olv)
{
    for (int e4 = unit * 2048 + threadIdx.x; e4 < (unit + 1) * 2048; e4 += 256) {
        int idx = e4 * 4, row = idx >> 7, col = idx & 127;
        float4 s0 = *(const float4*)(&P[0][idx]);
        float4 s1 = *(const float4*)(&P[1][idx]);
        float4 s2 = *(const float4*)(&P[2][idx]);
        float4 s3 = *(const float4*)(&P[3][idx]);
        float4 b  = *(const float4*)(bias + col);
        float4 v;
        v.x = s0.x+s1.x+s2.x+s3.x+b.x; v.y = s0.y+s1.y+s2.y+s3.y+b.y;
        v.z = s0.z+s1.z+s2.z+s3.z+b.z; v.w = s0.w+s1.w+s2.w+s3.w+b.w;
        if (col < 64) *(float4*)(om  + row * 64 + col)      = v;
        else          *(float4*)(olv + row * 64 + col - 64) = v;
    }
}

__device__ __forceinline__ void red_rec(int unit, const float (*P)[NB*OBS],
                                        const float* __restrict__ bias,
                                        float* __restrict__ out)
{
    for (int e4 = unit * 1024 + threadIdx.x; e4 < (unit + 1) * 1024; e4 += 256) {
        int idx = e4 * 4, col = idx & 127;
        float4 s0 = *(const float4*)(&P[0][idx]);
        float4 s1 = *(const float4*)(&P[1][idx]);
        float4 s2 = *(const float4*)(&P[2][idx]);
        float4 s3 = *(const float4*)(&P[3][idx]);
        float4 b  = *(const float4*)(bias + col);
        float4 v;
        v.x = s0.x+s1.x+s2.x+s3.x+b.x; v.y = s0.y+s1.y+s2.y+s3.y+b.y;
        v.z = s0.z+s1.z+s2.z+s3.z+b.z; v.w = s0.w+s1.w+s2.w+s3.w+b.w;
        *(float4*)(out + idx) = v;
    }
}

// ------------------------- phase-1 GEMM kernel ------------------------------
extern "C" __global__ void __launch_bounds__(256)
gemm128(const float* __restrict__ A, int lda,
        const float* __restrict__ W, int ldw,
        const float* __restrict__ bias,
        float* __restrict__ C, int ldc, int K, int doRelu)
{
    tile128(0, A, lda, 0, 0, 0, 0, 0, 0,
            W, ldw, 0, K / 64, blockIdx.y * 128, blockIdx.x * 64,
            C, ldc, bias, doRelu);
}

// ------------------------- persistent recurrent kernel ----------------------
extern "C" __global__ void __launch_bounds__(256)
vrnn_loop(const float* __restrict__ eps,
          const float* __restrict__ prior_w1, const float* __restrict__ prior_b1,
          const float* __restrict__ prior_w2, const float* __restrict__ prior_b2,
          const float* __restrict__ enc_w1,
          const float* __restrict__ enc_w2,  const float* __restrict__ enc_b2,
          const float* __restrict__ phi_z_w, const float* __restrict__ phi_z_b,
          const float* __restrict__ dec_w1,  const float* __restrict__ dec_b1,
          const float* __restrict__ dec_w2,  const float* __restrict__ dec_b2,
          const float* __restrict__ gru_wih, const float* __restrict__ gru_whh,
          const float* __restrict__ gru_bhh,
          float* __restrict__ out)
{
    float* out_rec  = out;
    float* out_prm  = out + (size_t)SEQT * NB * OBS;
    float* out_prlv = out_prm  + (size_t)SEQT * NB * LAT;
    float* out_pom  = out_prlv + (size_t)SEQT * NB * LAT;
    float* out_polv = out_pom  + (size_t)SEQT * NB * LAT;
    const int bid = blockIdx.x, grid = gridDim.x;

    for (int i = bid * 256 + threadIdx.x; i < NB * HID; i += grid * 256)
        g_h[0][i] = 0.f;
    grid_sync();

    for (int t = 0; t < SEQT; t++) {
        const float* h    = g_h[t & 1];
        float*       hnew = g_h[(t + 1) & 1];
        const float* epsT = eps + (size_t)t * NB * LAT;
        float (*D1hc)[NB*HID] = g_D1hp[t & 1];
        float (*D1hp)[NB*HID] = g_D1hp[(t ^ 1) & 1];

        // ---- S1 (148): E(32) | A(32) | GH 0..83 ----
        for (int u = bid; u < 148; u += grid) {
            if (u < 32) {
                int c = u & 3, i = u >> 2;
                tile128(0, h, HID, c*64, 0, 0, 0, 0, 0,
                        enc_w1 + HID, 2*HID, c*64, 1, (i>>2)*128, (i&3)*64,
                        g_Ep[c], HID, 0, 0);
            } else if (u < 64) {
                int w = u - 32, c = w & 3, i = w >> 2;
                tile128(0, h, HID, c*64, 0, 0, 0, 0, 0,
                        prior_w1, HID, c*64, 1, (i>>2)*128, (i&3)*64,
                        g_Ap[c], HID, 0, 0);
            } else {
                int gh = u - 64, c = gh & 3, i = gh >> 2;   // gh 0..83, i 0..20
                tile128(0, h, HID, c*64, 0, 0, 0, 0, 0,
                        gru_whh, HID, c*64, 1, (i/12)*128, (i%12)*64,
                        g_GHp[c], 3*HID, 0, 0);
            }
        }
        grid_sync();

        // ---- S2 (92): post(16) | prior2(16) | GH 84..95 | D1h(32) | decout(t-1)(16) ----
        {
            int cnt = (t > 0) ? 92 : 76;
            for (int u = bid; u < cnt; u += grid) {
                if (u < 16) {
                    int c = u & 3, i = u >> 2;
                    tile128(1, g_Ep[0], HID, c*64, 0, PSTR_H,
                            g_encx + (size_t)t*NB*HID, 0, 0,
                            enc_w2, HID, c*64, 1, (i>>1)*128, (i&1)*64,
                            g_postp[c], 128, 0, 0);
                } else if (u < 32) {
                    int w = u - 16, c = w & 3, i = w >> 2;
                    tile128(1, g_Ap[0], HID, c*64, 0, PSTR_H, 0, prior_b1, 0,
                            prior_w2, HID, c*64, 1, (i>>1)*128, (i&1)*64,
                            g_priorp[c], 128, 0, 0);
                } else if (u < 44) {
                    int gh = u - 32 + 84, c = gh & 3, i = gh >> 2;  // i 21..23
                    tile128(0, h, HID, c*64, 0, 0, 0, 0, 0,
                            gru_whh, HID, c*64, 1, (i/12)*128, (i%12)*64,
                            g_GHp[c], 3*HID, 0, 0);
                } else if (u < 76) {
                    int w = u - 44, c = w & 3, i = w >> 2;
                    tile128(0, h, HID, c*64, 0, 0, 0, 0, 0,
                            dec_w1 + HID, 2*HID, c*64, 1, (i>>2)*128, (i&3)*64,
                            D1hc[c], HID, 0, 0);
                } else {
                    int w = u - 76, c = w & 3, i = w >> 2;  // decout(t-1)
                    tile128(1, g_Dp[0], HID, c*64, D1hp[0], PSTR_H, 0, dec_b1, 0,
                            dec_w2, HID, c*64, 1, (i>>1)*128, (i&1)*64,
                            g_recp[c], OBS, 0, 0);
                }
            }
        }
        grid_sync();

        // ---- S3 (24): phiz ZGEN(8) | redPost(4) | redPrior(4) | redRec(t-1)(8) ----
        {
            int cnt = (t > 0) ? 24 : 16;
            for (int u = bid; u < cnt; u += grid) {
                if (u < 8) {
                    int i = u;
                    tile128(2, g_postp[0], 128, 0, 0, PSTR_L, 0, enc_b2, epsT,
                            phi_z_w, LAT, 0, 1, (i>>2)*128, (i&3)*64,
                            g_phiz, HID, phi_z_b, 1);
                } else if (u < 12) {
                    red_latent(u - 8, g_postp, enc_b2,
                               out_pom + (size_t)t*NB*LAT,
                               out_polv + (size_t)t*NB*LAT);
                } else if (u < 16) {
                    red_latent(u - 12, g_priorp, prior_b2,
                               out_prm + (size_t)t*NB*LAT,
                               out_prlv + (size_t)t*NB*LAT);
                } else {
                    red_rec(u - 16, g_recp, dec_b2,
                            out_rec + (size_t)(t-1)*NB*OBS);
                }
            }
        }
        grid_sync();

        // ---- S4 (128): gxz(96) | decL1(32) ----
        for (int u = bid; u < 128; u += grid) {
            if (u < 96) {
                int c = u & 3, i = u >> 2;
                tile128(0, g_phiz, HID, c*64, 0, 0, 0, 0, 0,
                        gru_wih + HID, 2*HID, c*64, 1, (i/12)*128, (i%12)*64,
                        g_gxzp[c], 3*HID, 0, 0);
            } else {
                int w = u - 96, c = w & 3, i = w >> 2;
                tile128(0, g_phiz, HID, c*64, 0, 0, 0, 0, 0,
                        dec_w1, 2*HID, c*64, 1, (i>>2)*128, (i&3)*64,
                        g_Dp[c], HID, 0, 0);
            }
        }
        grid_sync();

        // ---- S5: GRU gates (64 light units) ----
        {
            const float* gxx = g_gxx + (size_t)t * NB * 3 * HID;
            for (int u = bid; u < 64; u += grid) {
                int e4 = u * 256 + threadIdx.x;
                int idx = e4 * 4, b = idx >> 8, cc = idx & 255;
                const float* gx = gxx + b * 768;
                float4 xr = *(const float4*)(gx + cc);
                float4 xz = *(const float4*)(gx + 256 + cc);
                float4 xn = *(const float4*)(gx + 512 + cc);
                float4 hr = *(const float4*)(gru_bhh + cc);
                float4 hz = *(const float4*)(gru_bhh + 256 + cc);
                float4 hn = *(const float4*)(gru_bhh + 512 + cc);
#pragma unroll
                for (int c = 0; c < 4; c++) {
                    const float* gz = &g_gxzp[c][b * 768];
                    float4 a0 = *(const float4*)(gz + cc);
                    float4 a1 = *(const float4*)(gz + 256 + cc);
                    float4 a2 = *(const float4*)(gz + 512 + cc);
                    xr.x += a0.x; xr.y += a0.y; xr.z += a0.z; xr.w += a0.w;
                    xz.x += a1.x; xz.y += a1.y; xz.z += a1.z; xz.w += a1.w;
                    xn.x += a2.x; xn.y += a2.y; xn.z += a2.z; xn.w += a2.w;
                    const float* gh = &g_GHp[c][b * 768];
                    float4 b0 = *(const float4*)(gh + cc);
                    float4 b1 = *(const float4*)(gh + 256 + cc);
                    float4 b2 = *(const float4*)(gh + 512 + cc);
                    hr.x += b0.x; hr.y += b0.y; hr.z += b0.z; hr.w += b0.w;
                    hz.x += b1.x; hz.y += b1.y; hz.z += b1.z; hz.w += b1.w;
                    hn.x += b2.x; hn.y += b2.y; hn.z += b2.z; hn.w += b2.w;
                }
                float4 hold = *(const float4*)(h + idx);
                float4 o;
                float rg = 1.f/(1.f+expf(-(xr.x+hr.x)));
                float zg = 1.f/(1.f+expf(-(xz.x+hz.x)));
                float nn = tanhf(xn.x + rg*hn.x);
                o.x = (1.f-zg)*nn + zg*hold.x;
                rg = 1.f/(1.f+expf(-(xr.y+hr.y)));
                zg = 1.f/(1.f+expf(-(xz.y+hz.y)));
                nn = tanhf(xn.y + rg*hn.y);
                o.y = (1.f-zg)*nn + zg*hold.y;
                rg = 1.f/(1.f+expf(-(xr.z+hr.z)));
                zg = 1.f/(1.f+expf(-(xz.z+hz.z)));
                nn = tanhf(xn.z + rg*hn.z);
                o.z = (1.f-zg)*nn + zg*hold.z;
                rg = 1.f/(1.f+expf(-(xr.w+hr.w)));
                zg = 1.f/(1.f+expf(-(xz.w+hz.w)));
                nn = tanhf(xn.w + rg*hn.w);
                o.w = (1.f-zg)*nn + zg*hold.w;
                *(float4*)(hnew + idx) = o;
            }
        }
        grid_sync();
    }

    // ---- Tail 1: decout(511) ----
    for (int u = bid; u < 16; u += grid) {
        int c = u & 3, i = u >> 2;
        tile128(1, g_Dp[0], HID, c*64, g_D1hp[(SEQT-1)&1][0], PSTR_H, 0, dec_b1, 0,
                dec_w2, HID, c*64, 1, (i>>1)*128, (i&1)*64,
                g_recp[c], OBS, 0, 0);
    }
    grid_sync();
    // ---- Tail 2: redRec(511) ----
    for (int u = bid; u < 8; u += grid)
        red_rec(u, g_recp, dec_b2, out_rec + (size_t)(SEQT-1)*NB*OBS);
}

// ------------------------- host launcher ------------------------------------
extern "C" void kernel_launch(void* const* d_in, const int* in_sizes, int n_in,
                              void* d_out, int out_size)
{
    const float* x        = (const float*)d_in[0];
    const float* eps      = (const float*)d_in[1];
    const float* phi_x_w1 = (const float*)d_in[2];
    const float* phi_x_b1 = (const float*)d_in[3];
    const float* phi_x_w2 = (const float*)d_in[4];
    const float* phi_x_b2 = (const float*)d_in[5];
    const float* phi_z_w  = (const float*)d_in[6];
    const float* phi_z_b  = (const float*)d_in[7];
    const float* prior_w1 = (const float*)d_in[8];
    const float* prior_b1 = (const float*)d_in[9];
    const float* prior_w2 = (const float*)d_in[10];
    const float* prior_b2 = (const float*)d_in[11];
    const float* enc_w1   = (const float*)d_in[12];
    const float* enc_b1   = (const float*)d_in[13];
    const float* enc_w2   = (const float*)d_in[14];
    const float* enc_b2   = (const float*)d_in[15];
    const float* dec_w1   = (const float*)d_in[16];
    const float* dec_b1   = (const float*)d_in[17];
    const float* dec_w2   = (const float*)d_in[18];
    const float* dec_b2   = (const float*)d_in[19];
    const float* gru_wih  = (const float*)d_in[20];
    const float* gru_whh  = (const float*)d_in[21];
    const float* gru_bih  = (const float*)d_in[22];
    const float* gru_bhh  = (const float*)d_in[23];

    float *p_h1, *p_phix, *p_encx, *p_gxx;
    cudaGetSymbolAddress((void**)&p_h1,   g_h1);
    cudaGetSymbolAddress((void**)&p_phix, g_phix);
    cudaGetSymbolAddress((void**)&p_encx, g_encx);
    cudaGetSymbolAddress((void**)&p_gxx,  g_gxx);

    int nsm = 148;
    cudaDeviceGetAttribute(&nsm, cudaDevAttrMultiProcessorCount, 0);

    dim3 blk(256);
    // Phase 1: parallel GEMMs over all SEQ*B rows (1024 row tiles of 128)
    gemm128<<<dim3(4, 1024),  blk>>>(x,      OBS,  phi_x_w1, OBS,   phi_x_b1, p_h1,   HID,   OBS, 1);
    gemm128<<<dim3(4, 1024),  blk>>>(p_h1,   HID,  phi_x_w2, HID,   phi_x_b2, p_phix, HID,   HID, 0);
    gemm128<<<dim3(4, 1024),  blk>>>(p_phix, HID,  enc_w1,   2*HID, enc_b1,   p_encx, HID,   HID, 0);
    gemm128<<<dim3(12, 1024), blk>>>(p_phix, HID,  gru_wih,  2*HID, gru_bih,  p_gxx,  3*HID, HID, 0);

    // Phase 2: persistent recurrent kernel
    vrnn_loop<<<nsm, blk>>>(eps, prior_w1, prior_b1, prior_w2, prior_b2,
                            enc_w1, enc_w2, enc_b2, phi_z_w, phi_z_b,
                            dec_w1, dec_b1, dec_w2, dec_b2,
                            gru_wih, gru_whh, gru_bhh, (float*)d_out);
}

// round 7
// speedup vs baseline: 1.0037x; 1.0037x over previous
#include <cuda_runtime.h>
#include <math.h>

#define SEQT 512
#define NB   256
#define OBS  128
#define LAT  64
#define HID  256
#define MB   (SEQT*NB)
#define NT   512   // threads per block

// ------------------------- device scratch ----------------------------------
__device__ float g_h1   [(size_t)MB*HID];
__device__ float g_phix [(size_t)MB*HID];
__device__ float g_encx [(size_t)MB*HID];           // includes enc_b1
__device__ float g_gxx  [(size_t)MB*3*HID];         // includes gru_bih
__device__ float g_h    [2][NB*HID];
__device__ float g_Ep   [4][NB*HID];
__device__ float g_Ap   [4][NB*HID];
__device__ float g_GHp  [4][NB*3*HID];
__device__ float g_D1hp [2][4][NB*HID];
__device__ float g_postp[4][NB*2*LAT];
__device__ float g_priorp[4][NB*2*LAT];
__device__ float g_phiz [NB*HID];
__device__ float g_gxzp [4][NB*3*HID];
__device__ float g_Dp   [4][NB*HID];
__device__ float g_recp [4][NB*OBS];

__device__ unsigned          g_bar_cnt;
__device__ volatile unsigned g_bar_gen;

#define PSTR_H   ((size_t)NB*HID)
#define PSTR_L   ((size_t)NB*2*LAT)

// ------------------------- grid barrier ------------------------------------
__device__ __forceinline__ void grid_sync()
{
    __syncthreads();
    if (threadIdx.x == 0) {
        __threadfence();
        unsigned my = g_bar_gen;
        if (atomicAdd(&g_bar_cnt, 1u) == gridDim.x - 1u) {
            g_bar_cnt = 0u;
            __threadfence();
            g_bar_gen = my + 1u;
        } else {
            while (g_bar_gen == my) { __nanosleep(20); }
        }
        __threadfence();
    }
    __syncthreads();
}

// ------------------------- 128x64 GEMM tile, 512 threads --------------------
// C[row0..+128, col0..+64] = epi( Aop[rows, kA0..+64*nk] @ W[col0..+64, kW0..+64*nk]^T )
// aSel 0: plain A.   aSel 1: relu( sum4(A partials) [+sum4(B2)] [+add] [+abias] )
// aSel 2: z-gen: pm/pl = sum4(postp)+abias halves; z = pm + eps*exp(0.5*pl)
__device__ __noinline__ void tile128(
    int aSel,
    const float* __restrict__ A, size_t lda, int kA0,
    const float* __restrict__ B2, size_t pstr,
    const float* __restrict__ add, const float* __restrict__ abias,
    const float* __restrict__ epsT,
    const float* __restrict__ W, int ldw, int kW0,
    int nk, int row0, int col0,
    float* __restrict__ C, size_t ldc,
    const float* __restrict__ cbias, int crelu)
{
    __shared__ float sA[64*128];   // [k][row]
    __shared__ float sW[64*64];    // [k][col]
    const int tid = threadIdx.x;
    const int rA = tid & 127, qA = tid >> 7;   // A loader: row, k-phase (0..3)
    const int rW = tid & 63,  qW = tid >> 6;   // W loader: col, k-phase (0..7)
    const int r0 = (tid >> 4) << 2;            // compute: 4 rows (0..124)
    const int c0 = (tid & 15) << 2;            // compute: 4 cols

    float acc[16];
#pragma unroll
    for (int i = 0; i < 16; i++) acc[i] = 0.f;

    for (int kc = 0; kc < nk; kc++) {
        const int kA = kA0 + kc * 64, kW = kW0 + kc * 64;
        // ---- load A (4 float4/thread), transpose into k-major ----
#pragma unroll
        for (int j = 0; j < 4; j++) {
            int k = (qA + j * 4) * 4;
            float4 v;
            if (aSel == 0) {
                v = *(const float4*)(A + (size_t)(row0 + rA) * lda + kA + k);
            } else if (aSel == 1) {
                const float* p = A + (size_t)(row0 + rA) * lda + kA + k;
                float4 s0 = *(const float4*)(p);
                float4 s1 = *(const float4*)(p + pstr);
                float4 s2 = *(const float4*)(p + 2 * pstr);
                float4 s3 = *(const float4*)(p + 3 * pstr);
                v.x = s0.x+s1.x+s2.x+s3.x; v.y = s0.y+s1.y+s2.y+s3.y;
                v.z = s0.z+s1.z+s2.z+s3.z; v.w = s0.w+s1.w+s2.w+s3.w;
                if (B2) {
                    const float* p2 = B2 + (size_t)(row0 + rA) * lda + kA + k;
                    float4 t0 = *(const float4*)(p2);
                    float4 t1 = *(const float4*)(p2 + pstr);
                    float4 t2 = *(const float4*)(p2 + 2 * pstr);
                    float4 t3 = *(const float4*)(p2 + 3 * pstr);
                    v.x += t0.x+t1.x+t2.x+t3.x; v.y += t0.y+t1.y+t2.y+t3.y;
                    v.z += t0.z+t1.z+t2.z+t3.z; v.w += t0.w+t1.w+t2.w+t3.w;
                }
                if (add) {
                    float4 a4 = *(const float4*)(add + (size_t)(row0 + rA) * lda + kA + k);
                    v.x += a4.x; v.y += a4.y; v.z += a4.z; v.w += a4.w;
                }
                if (abias) {
                    float4 b4 = *(const float4*)(abias + kA + k);
                    v.x += b4.x; v.y += b4.y; v.z += b4.z; v.w += b4.w;
                }
                v.x = fmaxf(v.x, 0.f); v.y = fmaxf(v.y, 0.f);
                v.z = fmaxf(v.z, 0.f); v.w = fmaxf(v.w, 0.f);
            } else {
                int rg = row0 + rA;
                const float* pm0 = A + (size_t)rg * 128 + k;
                const float* pl0 = A + (size_t)rg * 128 + 64 + k;
                float4 m0 = *(const float4*)(pm0);
                float4 m1 = *(const float4*)(pm0 + pstr);
                float4 m2 = *(const float4*)(pm0 + 2 * pstr);
                float4 m3 = *(const float4*)(pm0 + 3 * pstr);
                float4 l0 = *(const float4*)(pl0);
                float4 l1 = *(const float4*)(pl0 + pstr);
                float4 l2 = *(const float4*)(pl0 + 2 * pstr);
                float4 l3 = *(const float4*)(pl0 + 3 * pstr);
                float4 bm = *(const float4*)(abias + k);
                float4 bl = *(const float4*)(abias + 64 + k);
                float4 ev = *(const float4*)(epsT + (size_t)rg * 64 + k);
                float pmx = m0.x+m1.x+m2.x+m3.x+bm.x, plx = l0.x+l1.x+l2.x+l3.x+bl.x;
                float pmy = m0.y+m1.y+m2.y+m3.y+bm.y, ply = l0.y+l1.y+l2.y+l3.y+bl.y;
                float pmz = m0.z+m1.z+m2.z+m3.z+bm.z, plz = l0.z+l1.z+l2.z+l3.z+bl.z;
                float pmw = m0.w+m1.w+m2.w+m3.w+bm.w, plw = l0.w+l1.w+l2.w+l3.w+bl.w;
                v.x = pmx + ev.x * expf(0.5f * plx);
                v.y = pmy + ev.y * expf(0.5f * ply);
                v.z = pmz + ev.z * expf(0.5f * plz);
                v.w = pmw + ev.w * expf(0.5f * plw);
            }
            sA[(k + 0) * 128 + rA] = v.x;
            sA[(k + 1) * 128 + rA] = v.y;
            sA[(k + 2) * 128 + rA] = v.z;
            sA[(k + 3) * 128 + rA] = v.w;
        }
        // ---- load W (2 float4/thread) ----
#pragma unroll
        for (int j = 0; j < 2; j++) {
            int k = (qW + j * 8) * 4;
            float4 wv = *(const float4*)(W + (size_t)(col0 + rW) * ldw + kW + k);
            sW[(k + 0) * 64 + rW] = wv.x;
            sW[(k + 1) * 64 + rW] = wv.y;
            sW[(k + 2) * 64 + rW] = wv.z;
            sW[(k + 3) * 64 + rW] = wv.w;
        }
        __syncthreads();
#pragma unroll 8
        for (int kk = 0; kk < 64; kk++) {
            float4 a = *(const float4*)(sA + kk * 128 + r0);
            float4 w = *(const float4*)(sW + kk * 64 + c0);
            acc[0]  += a.x*w.x; acc[1]  += a.x*w.y; acc[2]  += a.x*w.z; acc[3]  += a.x*w.w;
            acc[4]  += a.y*w.x; acc[5]  += a.y*w.y; acc[6]  += a.y*w.z; acc[7]  += a.y*w.w;
            acc[8]  += a.z*w.x; acc[9]  += a.z*w.y; acc[10] += a.z*w.z; acc[11] += a.z*w.w;
            acc[12] += a.w*w.x; acc[13] += a.w*w.y; acc[14] += a.w*w.z; acc[15] += a.w*w.w;
        }
        __syncthreads();
    }

    float4 cb = make_float4(0.f, 0.f, 0.f, 0.f);
    if (cbias) cb = *(const float4*)(cbias + col0 + c0);
#pragma unroll
    for (int i = 0; i < 4; i++) {
        size_t row = (size_t)(row0 + r0 + i);
        float4 v;
        v.x = acc[i*4+0] + cb.x; v.y = acc[i*4+1] + cb.y;
        v.z = acc[i*4+2] + cb.z; v.w = acc[i*4+3] + cb.w;
        if (crelu) {
            v.x = fmaxf(v.x, 0.f); v.y = fmaxf(v.y, 0.f);
            v.z = fmaxf(v.z, 0.f); v.w = fmaxf(v.w, 0.f);
        }
        *(float4*)(C + row * ldc + col0 + c0) = v;
    }
}

// ------------------------- reduce helpers (512 threads) ---------------------
__device__ __forceinline__ void red_latent(int unit, const float (*P)[NB*2*LAT],
                                           const float* __restrict__ bias,
                                           float* __restrict__ om, float* __restrict__ olv)
{
    for (int e4 = unit * 2048 + threadIdx.x; e4 < (unit + 1) * 2048; e4 += NT) {
        int idx = e4 * 4, row = idx >> 7, col = idx & 127;
        float4 s0 = *(const float4*)(&P[0][idx]);
        float4 s1 = *(const float4*)(&P[1][idx]);
        float4 s2 = *(const float4*)(&P[2][idx]);
        float4 s3 = *(const float4*)(&P[3][idx]);
        float4 b  = *(const float4*)(bias + col);
        float4 v;
        v.x = s0.x+s1.x+s2.x+s3.x+b.x; v.y = s0.y+s1.y+s2.y+s3.y+b.y;
        v.z = s0.z+s1.z+s2.z+s3.z+b.z; v.w = s0.w+s1.w+s2.w+s3.w+b.w;
        if (col < 64) *(float4*)(om  + row * 64 + col)      = v;
        else          *(float4*)(olv + row * 64 + col - 64) = v;
    }
}

__device__ __forceinline__ void red_rec(int unit, const float (*P)[NB*OBS],
                                        const float* __restrict__ bias,
                                        float* __restrict__ out)
{
    for (int e4 = unit * 1024 + threadIdx.x; e4 < (unit + 1) * 1024; e4 += NT) {
        int idx = e4 * 4, col = idx & 127;
        float4 s0 = *(const float4*)(&P[0][idx]);
        float4 s1 = *(const float4*)(&P[1][idx]);
        float4 s2 = *(const float4*)(&P[2][idx]);
        float4 s3 = *(const float4*)(&P[3][idx]);
        float4 b  = *(const float4*)(bias + col);
        float4 v;
        v.x = s0.x+s1.x+s2.x+s3.x+b.x; v.y = s0.y+s1.y+s2.y+s3.y+b.y;
        v.z = s0.z+s1.z+s2.z+s3.z+b.z; v.w = s0.w+s1.w+s2.w+s3.w+b.w;
        *(float4*)(out + idx) = v;
    }
}

// ------------------------- phase-1 GEMM kernel ------------------------------
extern "C" __global__ void __launch_bounds__(NT)
gemm128(const float* __restrict__ A, int lda,
        const float* __restrict__ W, int ldw,
        const float* __restrict__ bias,
        float* __restrict__ C, int ldc, int K, int doRelu)
{
    tile128(0, A, lda, 0, 0, 0, 0, 0, 0,
            W, ldw, 0, K / 64, blockIdx.y * 128, blockIdx.x * 64,
            C, ldc, bias, doRelu);
}

// ------------------------- persistent recurrent kernel ----------------------
extern "C" __global__ void __launch_bounds__(NT)
vrnn_loop(const float* __restrict__ eps,
          const float* __restrict__ prior_w1, const float* __restrict__ prior_b1,
          const float* __restrict__ prior_w2, const float* __restrict__ prior_b2,
          const float* __restrict__ enc_w1,
          const float* __restrict__ enc_w2,  const float* __restrict__ enc_b2,
          const float* __restrict__ phi_z_w, const float* __restrict__ phi_z_b,
          const float* __restrict__ dec_w1,  const float* __restrict__ dec_b1,
          const float* __restrict__ dec_w2,  const float* __restrict__ dec_b2,
          const float* __restrict__ gru_wih, const float* __restrict__ gru_whh,
          const float* __restrict__ gru_bhh,
          float* __restrict__ out)
{
    float* out_rec  = out;
    float* out_prm  = out + (size_t)SEQT * NB * OBS;
    float* out_prlv = out_prm  + (size_t)SEQT * NB * LAT;
    float* out_pom  = out_prlv + (size_t)SEQT * NB * LAT;
    float* out_polv = out_pom  + (size_t)SEQT * NB * LAT;
    const int bid = blockIdx.x, grid = gridDim.x;

    for (int i = bid * NT + threadIdx.x; i < NB * HID; i += grid * NT)
        g_h[0][i] = 0.f;
    grid_sync();

    for (int t = 0; t < SEQT; t++) {
        const float* h    = g_h[t & 1];
        float*       hnew = g_h[(t + 1) & 1];
        const float* epsT = eps + (size_t)t * NB * LAT;
        float (*D1hc)[NB*HID] = g_D1hp[t & 1];
        float (*D1hp)[NB*HID] = g_D1hp[(t ^ 1) & 1];

        // ---- S1 (148): E(32) | A(32) | GH 0..83 ----
        for (int u = bid; u < 148; u += grid) {
            if (u < 32) {
                int c = u & 3, i = u >> 2;
                tile128(0, h, HID, c*64, 0, 0, 0, 0, 0,
                        enc_w1 + HID, 2*HID, c*64, 1, (i>>2)*128, (i&3)*64,
                        g_Ep[c], HID, 0, 0);
            } else if (u < 64) {
                int w = u - 32, c = w & 3, i = w >> 2;
                tile128(0, h, HID, c*64, 0, 0, 0, 0, 0,
                        prior_w1, HID, c*64, 1, (i>>2)*128, (i&3)*64,
                        g_Ap[c], HID, 0, 0);
            } else {
                int gh = u - 64, c = gh & 3, i = gh >> 2;   // gh 0..83, i 0..20
                tile128(0, h, HID, c*64, 0, 0, 0, 0, 0,
                        gru_whh, HID, c*64, 1, (i/12)*128, (i%12)*64,
                        g_GHp[c], 3*HID, 0, 0);
            }
        }
        grid_sync();

        // ---- S2 (92): post(16) | prior2(16) | GH 84..95 | D1h(32) | decout(t-1)(16) ----
        {
            int cnt = (t > 0) ? 92 : 76;
            for (int u = bid; u < cnt; u += grid) {
                if (u < 16) {
                    int c = u & 3, i = u >> 2;
                    tile128(1, g_Ep[0], HID, c*64, 0, PSTR_H,
                            g_encx + (size_t)t*NB*HID, 0, 0,
                            enc_w2, HID, c*64, 1, (i>>1)*128, (i&1)*64,
                            g_postp[c], 128, 0, 0);
                } else if (u < 32) {
                    int w = u - 16, c = w & 3, i = w >> 2;
                    tile128(1, g_Ap[0], HID, c*64, 0, PSTR_H, 0, prior_b1, 0,
                            prior_w2, HID, c*64, 1, (i>>1)*128, (i&1)*64,
                            g_priorp[c], 128, 0, 0);
                } else if (u < 44) {
                    int gh = u - 32 + 84, c = gh & 3, i = gh >> 2;  // i 21..23
                    tile128(0, h, HID, c*64, 0, 0, 0, 0, 0,
                            gru_whh, HID, c*64, 1, (i/12)*128, (i%12)*64,
                            g_GHp[c], 3*HID, 0, 0);
                } else if (u < 76) {
                    int w = u - 44, c = w & 3, i = w >> 2;
                    tile128(0, h, HID, c*64, 0, 0, 0, 0, 0,
                            dec_w1 + HID, 2*HID, c*64, 1, (i>>2)*128, (i&3)*64,
                            D1hc[c], HID, 0, 0);
                } else {
                    int w = u - 76, c = w & 3, i = w >> 2;  // decout(t-1)
                    tile128(1, g_Dp[0], HID, c*64, D1hp[0], PSTR_H, 0, dec_b1, 0,
                            dec_w2, HID, c*64, 1, (i>>1)*128, (i&1)*64,
                            g_recp[c], OBS, 0, 0);
                }
            }
        }
        grid_sync();

        // ---- S3 (24): phiz ZGEN(8) | redPost(4) | redPrior(4) | redRec(t-1)(8) ----
        {
            int cnt = (t > 0) ? 24 : 16;
            for (int u = bid; u < cnt; u += grid) {
                if (u < 8) {
                    int i = u;
                    tile128(2, g_postp[0], 128, 0, 0, PSTR_L, 0, enc_b2, epsT,
                            phi_z_w, LAT, 0, 1, (i>>2)*128, (i&3)*64,
                            g_phiz, HID, phi_z_b, 1);
                } else if (u < 12) {
                    red_latent(u - 8, g_postp, enc_b2,
                               out_pom + (size_t)t*NB*LAT,
                               out_polv + (size_t)t*NB*LAT);
                } else if (u < 16) {
                    red_latent(u - 12, g_priorp, prior_b2,
                               out_prm + (size_t)t*NB*LAT,
                               out_prlv + (size_t)t*NB*LAT);
                } else {
                    red_rec(u - 16, g_recp, dec_b2,
                            out_rec + (size_t)(t-1)*NB*OBS);
                }
            }
        }
        grid_sync();

        // ---- S4 (128): gxz(96) | decL1(32) ----
        for (int u = bid; u < 128; u += grid) {
            if (u < 96) {
                int c = u & 3, i = u >> 2;
                tile128(0, g_phiz, HID, c*64, 0, 0, 0, 0, 0,
                        gru_wih + HID, 2*HID, c*64, 1, (i/12)*128, (i%12)*64,
                        g_gxzp[c], 3*HID, 0, 0);
            } else {
                int w = u - 96, c = w & 3, i = w >> 2;
                tile128(0, g_phiz, HID, c*64, 0, 0, 0, 0, 0,
                        dec_w1, 2*HID, c*64, 1, (i>>2)*128, (i&3)*64,
                        g_Dp[c], HID, 0, 0);
            }
        }
        grid_sync();

        // ---- S5: GRU gates (flat over NB*HID/4 float4) ----
        {
            const float* gxx = g_gxx + (size_t)t * NB * 3 * HID;
            for (int i4 = bid * NT + threadIdx.x; i4 < NB * HID / 4; i4 += grid * NT) {
                int idx = i4 * 4, b = idx >> 8, cc = idx & 255;
                const float* gx = gxx + b * 768;
                float4 xr = *(const float4*)(gx + cc);
                float4 xz = *(const float4*)(gx + 256 + cc);
                float4 xn = *(const float4*)(gx + 512 + cc);
                float4 hr = *(const float4*)(gru_bhh + cc);
                float4 hz = *(const float4*)(gru_bhh + 256 + cc);
                float4 hn = *(const float4*)(gru_bhh + 512 + cc);
#pragma unroll
                for (int c = 0; c < 4; c++) {
                    const float* gz = &g_gxzp[c][b * 768];
                    float4 a0 = *(const float4*)(gz + cc);
                    float4 a1 = *(const float4*)(gz + 256 + cc);
                    float4 a2 = *(const float4*)(gz + 512 + cc);
                    xr.x += a0.x; xr.y += a0.y; xr.z += a0.z; xr.w += a0.w;
                    xz.x += a1.x; xz.y += a1.y; xz.z += a1.z; xz.w += a1.w;
                    xn.x += a2.x; xn.y += a2.y; xn.z += a2.z; xn.w += a2.w;
                    const float* gh = &g_GHp[c][b * 768];
                    float4 b0 = *(const float4*)(gh + cc);
                    float4 b1 = *(const float4*)(gh + 256 + cc);
                    float4 b2 = *(const float4*)(gh + 512 + cc);
                    hr.x += b0.x; hr.y += b0.y; hr.z += b0.z; hr.w += b0.w;
                    hz.x += b1.x; hz.y += b1.y; hz.z += b1.z; hz.w += b1.w;
                    hn.x += b2.x; hn.y += b2.y; hn.z += b2.z; hn.w += b2.w;
                }
                float4 hold = *(const float4*)(h + idx);
                float4 o;
                float rg = 1.f/(1.f+expf(-(xr.x+hr.x)));
                float zg = 1.f/(1.f+expf(-(xz.x+hz.x)));
                float nn = tanhf(xn.x + rg*hn.x);
                o.x = (1.f-zg)*nn + zg*hold.x;
                rg = 1.f/(1.f+expf(-(xr.y+hr.y)));
                zg = 1.f/(1.f+expf(-(xz.y+hz.y)));
                nn = tanhf(xn.y + rg*hn.y);
                o.y = (1.f-zg)*nn + zg*hold.y;
                rg = 1.f/(1.f+expf(-(xr.z+hr.z)));
                zg = 1.f/(1.f+expf(-(xz.z+hz.z)));
                nn = tanhf(xn.z + rg*hn.z);
                o.z = (1.f-zg)*nn + zg*hold.z;
                rg = 1.f/(1.f+expf(-(xr.w+hr.w)));
                zg = 1.f/(1.f+expf(-(xz.w+hz.w)));
                nn = tanhf(xn.w + rg*hn.w);
                o.w = (1.f-zg)*nn + zg*hold.w;
                *(float4*)(hnew + idx) = o;
            }
        }
        grid_sync();
    }

    // ---- Tail 1: decout(511) ----
    for (int u = bid; u < 16; u += grid) {
        int c = u & 3, i = u >> 2;
        tile128(1, g_Dp[0], HID, c*64, g_D1hp[(SEQT-1)&1][0], PSTR_H, 0, dec_b1, 0,
                dec_w2, HID, c*64, 1, (i>>1)*128, (i&1)*64,
                g_recp[c], OBS, 0, 0);
    }
    grid_sync();
    // ---- Tail 2: redRec(511) ----
    for (int u = bid; u < 8; u += grid)
        red_rec(u, g_recp, dec_b2, out_rec + (size_t)(SEQT-1)*NB*OBS);
}

// ------------------------- host launcher ------------------------------------
extern "C" void kernel_launch(void* const* d_in, const int* in_sizes, int n_in,
                              void* d_out, int out_size)
{
    const float* x        = (const float*)d_in[0];
    const float* eps      = (const float*)d_in[1];
    const float* phi_x_w1 = (const float*)d_in[2];
    const float* phi_x_b1 = (const float*)d_in[3];
    const float* phi_x_w2 = (const float*)d_in[4];
    const float* phi_x_b2 = (const float*)d_in[5];
    const float* phi_z_w  = (const float*)d_in[6];
    const float* phi_z_b  = (const float*)d_in[7];
    const float* prior_w1 = (const float*)d_in[8];
    const float* prior_b1 = (const float*)d_in[9];
    const float* prior_w2 = (const float*)d_in[10];
    const float* prior_b2 = (const float*)d_in[11];
    const float* enc_w1   = (const float*)d_in[12];
    const float* enc_b1   = (const float*)d_in[13];
    const float* enc_w2   = (const float*)d_in[14];
    const float* enc_b2   = (const float*)d_in[15];
    const float* dec_w1   = (const float*)d_in[16];
    const float* dec_b1   = (const float*)d_in[17];
    const float* dec_w2   = (const float*)d_in[18];
    const float* dec_b2   = (const float*)d_in[19];
    const float* gru_wih  = (const float*)d_in[20];
    const float* gru_whh  = (const float*)d_in[21];
    const float* gru_bih  = (const float*)d_in[22];
    const float* gru_bhh  = (const float*)d_in[23];

    float *p_h1, *p_phix, *p_encx, *p_gxx;
    cudaGetSymbolAddress((void**)&p_h1,   g_h1);
    cudaGetSymbolAddress((void**)&p_phix, g_phix);
    cudaGetSymbolAddress((void**)&p_encx, g_encx);
    cudaGetSymbolAddress((void**)&p_gxx,  g_gxx);

    int nsm = 148;
    cudaDeviceGetAttribute(&nsm, cudaDevAttrMultiProcessorCount, 0);

    dim3 blk(NT);
    // Phase 1: parallel GEMMs over all SEQ*B rows (1024 row tiles of 128)
    gemm128<<<dim3(4, 1024),  blk>>>(x,      OBS,  phi_x_w1, OBS,   phi_x_b1, p_h1,   HID,   OBS, 1);
    gemm128<<<dim3(4, 1024),  blk>>>(p_h1,   HID,  phi_x_w2, HID,   phi_x_b2, p_phix, HID,   HID, 0);
    gemm128<<<dim3(4, 1024),  blk>>>(p_phix, HID,  enc_w1,   2*HID, enc_b1,   p_encx, HID,   HID, 0);
    gemm128<<<dim3(12, 1024), blk>>>(p_phix, HID,  gru_wih,  2*HID, gru_bih,  p_gxx,  3*HID, HID, 0);

    // Phase 2: persistent recurrent kernel
    vrnn_loop<<<nsm, blk>>>(eps, prior_w1, prior_b1, prior_w2, prior_b2,
                            enc_w1, enc_w2, enc_b2, phi_z_w, phi_z_b,
                            dec_w1, dec_b1, dec_w2, dec_b2,
                            gru_wih, gru_whh, gru_bhh, (float*)d_out);
}